// round 1
// baseline (speedup 1.0000x reference)
#include <cuda_runtime.h>
#include <cstdint>

#define NPTS 12288
#define DW   384           // 32-bit words per adjacency row (12288/32)
#define EPS2 0.25f
#define MIN_SAMPLES 5

// ---------------- device scratch (no dynamic allocation allowed) -------------
__device__ unsigned g_adj[NPTS * DW];   // 18.9 MB adjacency bitmap
__device__ float    g_sq[NPTS];         // squared norms
__device__ int      g_parent[NPTS];     // union-find parents
__device__ int      g_core[NPTS];       // core mask
__device__ unsigned g_corebits[DW];     // core mask, bit-packed
__device__ int      g_lbl[NPTS];        // flattened root per core (SENTINEL else)
__device__ int      g_root[NPTS];       // root per point (SENTINEL = noise)
__device__ int      g_rank[NPTS];       // cumsum(is_root)-1

// ---------------- K0: squared norms + parent init ----------------------------
__global__ void k_prep(const float* __restrict__ X) {
    int i = blockIdx.x * blockDim.x + threadIdx.x;
    if (i >= NPTS) return;
    const float4* xv = (const float4*)X;
    float4 a = xv[i * 2 + 0];
    float4 b = xv[i * 2 + 1];
    float s = a.x * a.x;
    s = fmaf(a.y, a.y, s);
    s = fmaf(a.z, a.z, s);
    s = fmaf(a.w, a.w, s);
    s = fmaf(b.x, b.x, s);
    s = fmaf(b.y, b.y, s);
    s = fmaf(b.z, b.z, s);
    s = fmaf(b.w, b.w, s);
    g_sq[i] = s;
    g_parent[i] = i;
}

// ---------------- K1: adjacency bitmap ---------------------------------------
// block = 256 threads (8 warps). Each block: 32 rows x 256 cols tile.
// warp w handles word column (blockIdx.x*8 + w); lane l handles row (blockIdx.y*32 + l).
__global__ void __launch_bounds__(256) k_adj(const float* __restrict__ X) {
    __shared__ float4 sxj[256 * 2];   // 256 j-points, 8 floats each
    __shared__ float  ssq[256];

    int t = threadIdx.x;
    int jbase = blockIdx.x * 256;
    const float4* xv = (const float4*)X;

    sxj[t * 2 + 0] = xv[(jbase + t) * 2 + 0];
    sxj[t * 2 + 1] = xv[(jbase + t) * 2 + 1];
    ssq[t] = g_sq[jbase + t];
    __syncthreads();

    int wid = t >> 5, lane = t & 31;
    int i = blockIdx.y * 32 + lane;
    float4 a = xv[i * 2 + 0];
    float4 b = xv[i * 2 + 1];
    float si = g_sq[i];

    int kb = wid * 32;
    unsigned bits = 0;
#pragma unroll
    for (int k = 0; k < 32; k++) {
        float4 c = sxj[(kb + k) * 2 + 0];
        float4 d = sxj[(kb + k) * 2 + 1];
        float dot = a.x * c.x;
        dot = fmaf(a.y, c.y, dot);
        dot = fmaf(a.z, c.z, dot);
        dot = fmaf(a.w, c.w, dot);
        dot = fmaf(b.x, d.x, dot);
        dot = fmaf(b.y, d.y, dot);
        dot = fmaf(b.z, d.z, dot);
        dot = fmaf(b.w, d.w, dot);
        float s = si + ssq[kb + k];
        float t2 = fmaf(-2.0f, dot, s);        // (sq_i + sq_j) - 2*dot, ref rounding
        if (t2 <= EPS2) bits |= (1u << k);
    }
    g_adj[i * DW + blockIdx.x * 8 + wid] = bits;
}

// ---------------- K2: density -> core mask (one warp per row) ----------------
__global__ void __launch_bounds__(256) k_core(void) {
    int wid = threadIdx.x >> 5, lane = threadIdx.x & 31;
    int i = blockIdx.x * 8 + wid;
    const unsigned* row = &g_adj[i * DW];
    int s = 0;
#pragma unroll
    for (int w = lane; w < DW; w += 32) s += __popc(row[w]);
#pragma unroll
    for (int o = 16; o; o >>= 1) s += __shfl_down_sync(0xffffffffu, s, o);
    if (lane == 0) g_core[i] = (s >= MIN_SAMPLES) ? 1 : 0;
}

// ---------------- K3: pack core mask into bitmap ------------------------------
__global__ void k_corebits(void) {
    int gw = blockIdx.x * 32 + (threadIdx.x >> 5);
    int lane = threadIdx.x & 31;
    unsigned b = __ballot_sync(0xffffffffu, g_core[gw * 32 + lane] != 0);
    if (lane == 0) g_corebits[gw] = b;
}

// ---------------- union-find -------------------------------------------------
__device__ __forceinline__ int uf_find(volatile int* p, int x) {
    int px = p[x];
    while (px != x) {
        int g = p[px];
        if (g != px) p[x] = g;   // path halving; benign race
        x = g;
        px = p[x];
    }
    return x;
}

__device__ __forceinline__ void uf_union(int* p, int a, int b) {
    volatile int* vp = p;
    while (true) {
        a = uf_find(vp, a);
        b = uf_find(vp, b);
        if (a == b) return;
        int hi = a > b ? a : b;
        int lo = a > b ? b : a;
        int old = atomicCAS(&p[hi], hi, lo);
        if (old == hi) return;   // hooked larger root under smaller -> root = min idx
        a = lo; b = old;
    }
}

// ---------------- K4: union over core-core edges (j > i once) ----------------
__global__ void __launch_bounds__(128) k_union(void) {
    int i = blockIdx.y;
    if (!g_core[i]) return;
    int w = blockIdx.x * 128 + threadIdx.x;   // gridDim.x = 3 -> w in [0,384)
    int iw = i >> 5;
    if (w < iw) return;                       // whole word has j <= i
    unsigned word = g_adj[i * DW + w] & g_corebits[w];
    if (w == iw) {
        int r = i & 31;
        word &= (r == 31) ? 0u : (0xffffffffu << (r + 1));   // keep only j > i
    }
    while (word) {
        int bpos = __ffs(word) - 1;
        word &= word - 1;
        uf_union(g_parent, i, w * 32 + bpos);
    }
}

// ---------------- K5: flatten roots ------------------------------------------
__device__ __forceinline__ int uf_find_ro(const volatile int* p, int x) {
    int px;
    while ((px = p[x]) != x) x = px;
    return x;
}

__global__ void k_flatten(void) {
    int i = blockIdx.x * blockDim.x + threadIdx.x;
    if (i >= NPTS) return;
    if (g_core[i]) {
        int r = uf_find_ro(g_parent, i);
        g_lbl[i] = r;
        g_root[i] = r;
    } else {
        g_lbl[i] = NPTS;   // SENTINEL for non-core
    }
}

// ---------------- K6: border assignment (one warp per non-core row) ----------
__global__ void __launch_bounds__(256) k_border(void) {
    int wid = threadIdx.x >> 5, lane = threadIdx.x & 31;
    int i = blockIdx.x * 8 + wid;
    if (g_core[i]) return;
    const unsigned* row = &g_adj[i * DW];
    int m = NPTS;
#pragma unroll
    for (int w = lane; w < DW; w += 32) {
        unsigned word = row[w] & g_corebits[w];
        while (word) {
            int bpos = __ffs(word) - 1;
            word &= word - 1;
            int l = g_lbl[w * 32 + bpos];
            m = min(m, l);
        }
    }
#pragma unroll
    for (int o = 16; o; o >>= 1) m = min(m, __shfl_down_sync(0xffffffffu, m, o));
    if (lane == 0) g_root[i] = m;   // NPTS = noise
}

// ---------------- K7: rank scan + final labels (single block) ----------------
__global__ void __launch_bounds__(1024) k_final(int* __restrict__ labels) {
    __shared__ int buf[1024];
    __shared__ int s_carry;
    int t = threadIdx.x;
    if (t == 0) s_carry = 0;
    __syncthreads();

    for (int c = 0; c < 12; c++) {
        int e = c * 1024 + t;
        int v = (g_core[e] && g_lbl[e] == e) ? 1 : 0;
        buf[t] = v;
        __syncthreads();
        for (int off = 1; off < 1024; off <<= 1) {
            int x = (t >= off) ? buf[t - off] : 0;
            __syncthreads();
            buf[t] += x;
            __syncthreads();
        }
        g_rank[e] = buf[t] + s_carry - 1;   // inclusive cumsum - 1
        __syncthreads();
        if (t == 1023) s_carry += buf[1023];
        __syncthreads();
    }

    // all g_rank writes from this block are visible after __syncthreads
    for (int c = 0; c < 12; c++) {
        int e = c * 1024 + t;
        int r = g_root[e];
        labels[e] = (r < NPTS) ? g_rank[r] : -1;
    }
}

// ---------------- launcher ----------------------------------------------------
extern "C" void kernel_launch(void* const* d_in, const int* in_sizes, int n_in,
                              void* d_out, int out_size) {
    const float* X = (const float*)d_in[0];
    int* labels = (int*)d_out;

    k_prep<<<48, 256>>>(X);
    k_adj<<<dim3(48, 384), 256>>>(X);
    k_core<<<NPTS / 8, 256>>>();
    k_corebits<<<12, 1024>>>();
    k_union<<<dim3(3, NPTS), 128>>>();
    k_flatten<<<48, 256>>>();
    k_border<<<NPTS / 8, 256>>>();
    k_final<<<1, 1024>>>(labels);
}

// round 2
// speedup vs baseline: 1.2034x; 1.2034x over previous
#include <cuda_runtime.h>
#include <cstdint>

#define NPTS 12288
#define DW   384           // 32-bit words per adjacency row (12288/32)
#define EPS2 0.25f
#define MIN_SAMPLES 5

// ---------------- device scratch (no dynamic allocation allowed) -------------
__device__ unsigned g_adj[NPTS * DW];   // 18.9 MB adjacency bitmap (L2-resident)
__device__ int      g_parent[NPTS];     // union-find parents
__device__ int      g_core[NPTS];       // core mask
__device__ unsigned g_corebits[DW];     // core mask, bit-packed
__device__ int      g_lbl[NPTS];        // flattened root per core (SENTINEL else)
__device__ int      g_root[NPTS];       // root per point (SENTINEL = noise)
__device__ int      g_rank[NPTS];       // cumsum(is_root)-1

// ---------------- f32x2 packed-math helpers (sm_100+) ------------------------
__device__ __forceinline__ unsigned long long pack2(float lo, float hi) {
    unsigned long long r;
    asm("mov.b64 %0, {%1, %2};" : "=l"(r) : "f"(lo), "f"(hi));
    return r;
}
__device__ __forceinline__ unsigned long long mul2(unsigned long long a, unsigned long long b) {
    unsigned long long d;
    asm("mul.rn.f32x2 %0, %1, %2;" : "=l"(d) : "l"(a), "l"(b));
    return d;
}
__device__ __forceinline__ unsigned long long fma2(unsigned long long a, unsigned long long b,
                                                   unsigned long long c) {
    unsigned long long d;
    asm("fma.rn.f32x2 %0, %1, %2, %3;" : "=l"(d) : "l"(a), "l"(b), "l"(c));
    return d;
}
__device__ __forceinline__ void unpack2(unsigned long long v, float& lo, float& hi) {
    asm("mov.b64 {%0, %1}, %2;" : "=f"(lo), "=f"(hi) : "l"(v));
}

// squared norm with the same sequential FMA chain as the distance dot products
__device__ __forceinline__ float norm8(float4 a, float4 b) {
    float s = a.x * a.x;
    s = fmaf(a.y, a.y, s);
    s = fmaf(a.z, a.z, s);
    s = fmaf(a.w, a.w, s);
    s = fmaf(b.x, b.x, s);
    s = fmaf(b.y, b.y, s);
    s = fmaf(b.z, b.z, s);
    s = fmaf(b.w, b.w, s);
    return s;
}

// ---------------- K1: adjacency bitmap ---------------------------------------
// block = 256 threads (8 warps). Tile: 128 i-rows x 256 j-cols.
// Warp w owns word column (blockIdx.x*8 + w); lane l owns rows
// base+l, +32, +64, +96 (4 rows). Row-pairs share packed f32x2 FMAs that keep
// the exact per-row sequential rounding order (mul dim0, then fma dims 1..7).
__global__ void __launch_bounds__(256) k_adj(const float* __restrict__ X) {
    __shared__ float4 sxj[256 * 2];   // 256 j-points
    __shared__ float  ssq[256];

    int t = threadIdx.x;
    int jbase = blockIdx.x * 256;
    const float4* xv = (const float4*)X;

    float4 jc0 = xv[(jbase + t) * 2 + 0];
    float4 jc1 = xv[(jbase + t) * 2 + 1];
    sxj[t * 2 + 0] = jc0;
    sxj[t * 2 + 1] = jc1;
    ssq[t] = norm8(jc0, jc1);
    __syncthreads();

    int wid = t >> 5, lane = t & 31;
    int i0 = blockIdx.y * 128 + lane;

    // load 4 i-rows, compute norms, pack row-pairs (0,1) and (2,3) per dim
    unsigned long long p0[8], p1[8];
    float si[4];
    {
        float4 a0 = xv[(i0 +  0) * 2 + 0], b0 = xv[(i0 +  0) * 2 + 1];
        float4 a1 = xv[(i0 + 32) * 2 + 0], b1 = xv[(i0 + 32) * 2 + 1];
        float4 a2 = xv[(i0 + 64) * 2 + 0], b2 = xv[(i0 + 64) * 2 + 1];
        float4 a3 = xv[(i0 + 96) * 2 + 0], b3 = xv[(i0 + 96) * 2 + 1];
        si[0] = norm8(a0, b0); si[1] = norm8(a1, b1);
        si[2] = norm8(a2, b2); si[3] = norm8(a3, b3);
        p0[0] = pack2(a0.x, a1.x); p0[1] = pack2(a0.y, a1.y);
        p0[2] = pack2(a0.z, a1.z); p0[3] = pack2(a0.w, a1.w);
        p0[4] = pack2(b0.x, b1.x); p0[5] = pack2(b0.y, b1.y);
        p0[6] = pack2(b0.z, b1.z); p0[7] = pack2(b0.w, b1.w);
        p1[0] = pack2(a2.x, a3.x); p1[1] = pack2(a2.y, a3.y);
        p1[2] = pack2(a2.z, a3.z); p1[3] = pack2(a2.w, a3.w);
        p1[4] = pack2(b2.x, b3.x); p1[5] = pack2(b2.y, b3.y);
        p1[6] = pack2(b2.z, b3.z); p1[7] = pack2(b2.w, b3.w);
    }

    int kb = wid * 32;
    unsigned bits0 = 0, bits1 = 0, bits2 = 0, bits3 = 0;
#pragma unroll 8
    for (int k = 0; k < 32; k++) {
        float4 c = sxj[(kb + k) * 2 + 0];
        float4 d = sxj[(kb + k) * 2 + 1];
        unsigned long long q0 = pack2(c.x, c.x), q1 = pack2(c.y, c.y);
        unsigned long long q2 = pack2(c.z, c.z), q3 = pack2(c.w, c.w);
        unsigned long long q4 = pack2(d.x, d.x), q5 = pack2(d.y, d.y);
        unsigned long long q6 = pack2(d.z, d.z), q7 = pack2(d.w, d.w);

        unsigned long long acc0 = mul2(p0[0], q0);
        acc0 = fma2(p0[1], q1, acc0); acc0 = fma2(p0[2], q2, acc0);
        acc0 = fma2(p0[3], q3, acc0); acc0 = fma2(p0[4], q4, acc0);
        acc0 = fma2(p0[5], q5, acc0); acc0 = fma2(p0[6], q6, acc0);
        acc0 = fma2(p0[7], q7, acc0);
        unsigned long long acc1 = mul2(p1[0], q0);
        acc1 = fma2(p1[1], q1, acc1); acc1 = fma2(p1[2], q2, acc1);
        acc1 = fma2(p1[3], q3, acc1); acc1 = fma2(p1[4], q4, acc1);
        acc1 = fma2(p1[5], q5, acc1); acc1 = fma2(p1[6], q6, acc1);
        acc1 = fma2(p1[7], q7, acc1);

        float d00, d01, d10, d11;
        unpack2(acc0, d00, d01);
        unpack2(acc1, d10, d11);
        float s = ssq[kb + k];
        if (fmaf(-2.0f, d00, si[0] + s) <= EPS2) bits0 |= (1u << k);
        if (fmaf(-2.0f, d01, si[1] + s) <= EPS2) bits1 |= (1u << k);
        if (fmaf(-2.0f, d10, si[2] + s) <= EPS2) bits2 |= (1u << k);
        if (fmaf(-2.0f, d11, si[3] + s) <= EPS2) bits3 |= (1u << k);
    }
    int col = blockIdx.x * 8 + wid;
    g_adj[(i0 +  0) * DW + col] = bits0;
    g_adj[(i0 + 32) * DW + col] = bits1;
    g_adj[(i0 + 64) * DW + col] = bits2;
    g_adj[(i0 + 96) * DW + col] = bits3;
}

// ---------------- K2: density -> core mask + bit-pack + parent init ----------
// grid = 384 blocks x 1024 threads; one warp per row, 32 rows per block.
__global__ void __launch_bounds__(1024) k_core(void) {
    __shared__ int sc[32];
    int wid = threadIdx.x >> 5, lane = threadIdx.x & 31;
    int i = blockIdx.x * 32 + wid;
    const unsigned* row = &g_adj[i * DW];
    int s = 0;
#pragma unroll
    for (int w = lane; w < DW; w += 32) s += __popc(row[w]);
#pragma unroll
    for (int o = 16; o; o >>= 1) s += __shfl_down_sync(0xffffffffu, s, o);
    if (lane == 0) {
        int c = (s >= MIN_SAMPLES) ? 1 : 0;
        sc[wid] = c;
        g_core[i] = c;
        g_parent[i] = i;
    }
    __syncthreads();
    if (wid == 0) {
        unsigned b = __ballot_sync(0xffffffffu, sc[lane] != 0);
        if (lane == 0) g_corebits[blockIdx.x] = b;
    }
}

// ---------------- union-find -------------------------------------------------
__device__ __forceinline__ int uf_find(volatile int* p, int x) {
    int px = p[x];
    while (px != x) {
        int g = p[px];
        if (g != px) p[x] = g;   // path halving; benign race
        x = g;
        px = p[x];
    }
    return x;
}

__device__ __forceinline__ void uf_union(int* p, int a, int b) {
    volatile int* vp = p;
    while (true) {
        a = uf_find(vp, a);
        b = uf_find(vp, b);
        if (a == b) return;
        int hi = a > b ? a : b;
        int lo = a > b ? b : a;
        int old = atomicCAS(&p[hi], hi, lo);
        if (old == hi) return;   // hooked larger root under smaller -> root = min idx
        a = lo; b = old;
    }
}

// ---------------- K3: union over core-core edges (j > i once) ----------------
// one warp per row; lanes stride over word columns >= i's word.
__global__ void __launch_bounds__(256) k_union(void) {
    int wid = threadIdx.x >> 5, lane = threadIdx.x & 31;
    int i = blockIdx.x * 8 + wid;
    if (!g_core[i]) return;
    int iw = i >> 5;
    for (int w = iw + lane; w < DW; w += 32) {
        unsigned word = g_adj[i * DW + w] & g_corebits[w];
        if (w == iw) {
            int r = i & 31;
            word &= (r == 31) ? 0u : (0xffffffffu << (r + 1));   // keep only j > i
        }
        while (word) {
            int bpos = __ffs(word) - 1;
            word &= word - 1;
            uf_union(g_parent, i, w * 32 + bpos);
        }
    }
}

// ---------------- K4: flatten roots ------------------------------------------
__device__ __forceinline__ int uf_find_ro(const volatile int* p, int x) {
    int px;
    while ((px = p[x]) != x) x = px;
    return x;
}

__global__ void k_flatten(void) {
    int i = blockIdx.x * blockDim.x + threadIdx.x;
    if (i >= NPTS) return;
    if (g_core[i]) {
        int r = uf_find_ro(g_parent, i);
        g_lbl[i] = r;
        g_root[i] = r;
    } else {
        g_lbl[i] = NPTS;   // SENTINEL for non-core
    }
}

// ---------------- K5: border assignment (one warp per non-core row) ----------
__global__ void __launch_bounds__(256) k_border(void) {
    int wid = threadIdx.x >> 5, lane = threadIdx.x & 31;
    int i = blockIdx.x * 8 + wid;
    if (g_core[i]) return;
    const unsigned* row = &g_adj[i * DW];
    int m = NPTS;
#pragma unroll
    for (int w = lane; w < DW; w += 32) {
        unsigned word = row[w] & g_corebits[w];
        while (word) {
            int bpos = __ffs(word) - 1;
            word &= word - 1;
            int l = g_lbl[w * 32 + bpos];
            m = min(m, l);
        }
    }
#pragma unroll
    for (int o = 16; o; o >>= 1) m = min(m, __shfl_down_sync(0xffffffffu, m, o));
    if (lane == 0) g_root[i] = m;   // NPTS = noise
}

// ---------------- K6: rank scan + final labels (single block, ballot scan) ---
__global__ void __launch_bounds__(1024) k_final(int* __restrict__ labels) {
    __shared__ int wsum[32];
    __shared__ int s_carry;
    int t = threadIdx.x, wid = t >> 5, lane = t & 31;
    if (t == 0) s_carry = 0;
    __syncthreads();

    for (int c = 0; c < 12; c++) {
        int e = c * 1024 + t;
        int v = (g_core[e] && g_lbl[e] == e) ? 1 : 0;
        unsigned bal = __ballot_sync(0xffffffffu, v);
        int pre = __popc(bal & (0xffffffffu >> (31 - lane)));   // inclusive prefix
        if (lane == 31) wsum[wid] = pre;                         // warp total
        __syncthreads();
        if (wid == 0) {
            int x = wsum[lane];
#pragma unroll
            for (int o = 1; o < 32; o <<= 1) {
                int y = __shfl_up_sync(0xffffffffu, x, o);
                if (lane >= o) x += y;
            }
            wsum[lane] = x;   // inclusive warp-total scan
        }
        __syncthreads();
        int base = s_carry + ((wid > 0) ? wsum[wid - 1] : 0);
        g_rank[e] = base + pre - 1;   // inclusive cumsum - 1
        __syncthreads();
        if (t == 0) s_carry += wsum[31];
        __syncthreads();
    }

    for (int c = 0; c < 12; c++) {
        int e = c * 1024 + t;
        int r = g_root[e];
        labels[e] = (r < NPTS) ? g_rank[r] : -1;
    }
}

// ---------------- launcher ----------------------------------------------------
extern "C" void kernel_launch(void* const* d_in, const int* in_sizes, int n_in,
                              void* d_out, int out_size) {
    (void)in_sizes; (void)n_in; (void)out_size;
    const float* X = (const float*)d_in[0];
    int* labels = (int*)d_out;

    k_adj<<<dim3(48, 96), 256>>>(X);
    k_core<<<384, 1024>>>();
    k_union<<<NPTS / 8, 256>>>();
    k_flatten<<<12, 1024>>>();
    k_border<<<NPTS / 8, 256>>>();
    k_final<<<1, 1024>>>(labels);
}